// round 4
// baseline (speedup 1.0000x reference)
#include <cuda_runtime.h>
#include <cstdint>

// ---------------- problem constants ----------------
#define B_IMG   2
#define N_PROP  2000
#define N_GT    16
#define NPROPS  2016          // N_PROP + N_GT
#define C_FEAT  256
#define HF      128
#define WF      128
#define BPI     512
#define NPOS_MAX 128
#define HID     1024
#define DIN     12544         // C_FEAT * 7 * 7
#define NSAMP   1024          // B_IMG * BPI

// ---------------- device scratch (no allocations allowed) ----------------
__device__ float g_props  [B_IMG * NPROPS * 4];
__device__ int   g_match  [B_IMG * NPROPS];
__device__ int   g_lab    [B_IMG * NPROPS];
__device__ float g_rand   [B_IMG * NPROPS];
__device__ float g_boxes  [NSAMP * 4];
__device__ int   g_labels [NSAMP];
__device__ float g_targets[NSAMP * 6];
__device__ __align__(16) float g_pooled[NSAMP * DIN];   // 51.4 MB
__device__ __align__(16) float g_x1[NSAMP * HID];
__device__ __align__(16) float g_x2[NSAMP * HID];
__device__ float g_logits [NSAMP * 2];
__device__ float g_reg    [NSAMP * 12];

// ---------------- threefry2x32 with key = (0, 42) (jax.random.key(42)) ----------------
__device__ __forceinline__ uint32_t rotl32(uint32_t x, int r) {
    return (x << r) | (x >> (32 - r));
}

__device__ __forceinline__ void threefry_0_42(uint32_t c0, uint32_t c1,
                                              uint32_t& o0, uint32_t& o1) {
    const uint32_t k0 = 0u, k1 = 42u, k2 = 0x1BD11BDAu ^ 0u ^ 42u;
    uint32_t x0 = c0 + k0, x1 = c1 + k1;
#define TFR(r) { x0 += x1; x1 = rotl32(x1, r); x1 ^= x0; }
    TFR(13) TFR(15) TFR(26) TFR(6)   x0 += k1; x1 += k2 + 1u;
    TFR(17) TFR(29) TFR(16) TFR(24)  x0 += k2; x1 += k0 + 2u;
    TFR(13) TFR(15) TFR(26) TFR(6)   x0 += k0; x1 += k1 + 3u;
    TFR(17) TFR(29) TFR(16) TFR(24)  x0 += k1; x1 += k2 + 4u;
    TFR(13) TFR(15) TFR(26) TFR(6)   x0 += k2; x1 += k0 + 5u;
#undef TFR
    o0 = x0; o1 = x1;
}

// ---------------- kernel 1: props + IoU match + label + jax rand ----------------
__global__ void k_prep(const float* __restrict__ proposals,
                       const float* __restrict__ gt_boxes,
                       const int*   __restrict__ gt_labels) {
    int b = blockIdx.y;
    int p = blockIdx.x * blockDim.x + threadIdx.x;

    __shared__ float sg[N_GT * 4];
    __shared__ float sga[N_GT];
    __shared__ int   sgl[N_GT];
    if (threadIdx.x < N_GT) {
        int g = threadIdx.x;
        float gx1 = gt_boxes[(b * N_GT + g) * 4 + 0];
        float gy1 = gt_boxes[(b * N_GT + g) * 4 + 1];
        float gx2 = gt_boxes[(b * N_GT + g) * 4 + 2];
        float gy2 = gt_boxes[(b * N_GT + g) * 4 + 3];
        sg[g * 4 + 0] = gx1; sg[g * 4 + 1] = gy1;
        sg[g * 4 + 2] = gx2; sg[g * 4 + 3] = gy2;
        sga[g] = (gx2 - gx1) * (gy2 - gy1);
        sgl[g] = gt_labels[b * N_GT + g];
    }
    __syncthreads();
    if (p >= NPROPS) return;

    float px1, py1, px2, py2;
    if (p < N_PROP) {
        const float* pp = proposals + (size_t)(b * N_PROP + p) * 4;
        px1 = pp[0]; py1 = pp[1]; px2 = pp[2]; py2 = pp[3];
    } else {
        int g = p - N_PROP;
        px1 = sg[g * 4 + 0]; py1 = sg[g * 4 + 1];
        px2 = sg[g * 4 + 2]; py2 = sg[g * 4 + 3];
    }
    int n = b * NPROPS + p;
    g_props[n * 4 + 0] = px1; g_props[n * 4 + 1] = py1;
    g_props[n * 4 + 2] = px2; g_props[n * 4 + 3] = py2;

    float ap = (px2 - px1) * (py2 - py1);
    float best = -1.0f; int bi = 0;
#pragma unroll
    for (int g = 0; g < N_GT; g++) {
        float ltx = fmaxf(sg[g * 4 + 0], px1);
        float lty = fmaxf(sg[g * 4 + 1], py1);
        float rbx = fminf(sg[g * 4 + 2], px2);
        float rby = fminf(sg[g * 4 + 3], py2);
        float w = fmaxf(rbx - ltx, 0.0f);
        float h = fmaxf(rby - lty, 0.0f);
        float inter = w * h;
        float iou = inter / (sga[g] + ap - inter);
        if (iou > best) { best = iou; bi = g; }   // strict > keeps first max (jax argmax)
    }
    g_match[n] = bi;
    g_lab[n]   = (best < 0.5f) ? 0 : sgl[bi];

    // jax.random.uniform(key(42), (2, 2016)) — PARTITIONABLE threefry
    // (jax_threefry_partitionable defaults to True since JAX 0.4.36):
    //   counter = (hi32(n), lo32(n)) = (0, n);  bits = out0 ^ out1
    uint32_t o0, o1;
    threefry_0_42(0u, (uint32_t)n, o0, o1);
    uint32_t bits = o0 ^ o1;
    g_rand[n] = __uint_as_float((bits >> 9) | 0x3f800000u) - 1.0f;
}

// ---------------- kernel 2: sampling (two bitonic sorts) + gather + encode ----------------
__device__ __forceinline__ unsigned long long pack_key(float f, int i) {
    uint32_t u = __float_as_uint(f);
    u = (u & 0x80000000u) ? ~u : (u | 0x80000000u);   // order-preserving transform
    return ((unsigned long long)u << 32) | (uint32_t)(0x7FF - i);  // lower index wins ties
}

__device__ void bitonic_desc(unsigned long long* keys, int tid) {
    for (int k = 2; k <= 2048; k <<= 1) {
        for (int j = k >> 1; j > 0; j >>= 1) {
            __syncthreads();
            for (int t = tid; t < 2048; t += 1024) {
                int ixj = t ^ j;
                if (ixj > t) {
                    unsigned long long a = keys[t], c = keys[ixj];
                    bool descBlk = ((t & k) == 0);
                    if (descBlk ? (a < c) : (a > c)) { keys[t] = c; keys[ixj] = a; }
                }
            }
        }
    }
    __syncthreads();
}

__global__ __launch_bounds__(1024) void k_sample(const float* __restrict__ gt_ellipses) {
    int b = blockIdx.x;
    int tid = threadIdx.x;
    __shared__ unsigned long long keys[2048];
    __shared__ unsigned char cap[2048];

    // phase 1: rank positives by rand (descending), cap at 128
    for (int i = tid; i < 2048; i += 1024) {
        cap[i] = 0;
        unsigned long long kv = 0ull;
        if (i < NPROPS) {
            float r = g_rand[b * NPROPS + i];
            float s = (g_lab[b * NPROPS + i] > 0) ? r : -1e9f;
            kv = pack_key(s, i);
        }
        keys[i] = kv;
    }
    __syncthreads();
    bitonic_desc(keys, tid);
    if (tid < NPOS_MAX) {
        unsigned long long kv = keys[tid];
        if (kv) {
            int i = 0x7FF - (int)(uint32_t)(kv & 0xFFFFFFFFull);
            if (i >= 0 && i < NPROPS && g_lab[b * NPROPS + i] > 0) cap[i] = 1;
        }
    }
    __syncthreads();

    // phase 2: prio = capped ? rand+2 : (neg ? rand : -1e9); select top-512 set
    for (int i = tid; i < 2048; i += 1024) {
        unsigned long long kv = 0ull;
        if (i < NPROPS) {
            float r = g_rand[b * NPROPS + i];
            float prio = cap[i] ? (r + 2.0f)
                                : ((g_lab[b * NPROPS + i] == 0) ? r : -1e9f);
            kv = pack_key(prio, i);
        }
        keys[i] = kv;
    }
    __syncthreads();
    bitonic_desc(keys, tid);

    if (tid < BPI) {
        int i   = 0x7FF - (int)(uint32_t)(keys[tid] & 0xFFFFFFFFull);
        int n   = b * BPI + tid;
        int src = b * NPROPS + i;
        float x1 = g_props[src * 4 + 0], y1 = g_props[src * 4 + 1];
        float x2 = g_props[src * 4 + 2], y2 = g_props[src * 4 + 3];
        g_boxes[n * 4 + 0] = x1; g_boxes[n * 4 + 1] = y1;
        g_boxes[n * 4 + 2] = x2; g_boxes[n * 4 + 3] = y2;
        int lab = g_lab[src];
        g_labels[n] = lab;
        int m = g_match[src];
        const float* el = gt_ellipses + (size_t)(b * N_GT + m) * 5;
        float ea = el[0], eb = el[1], ex = el[2], ey = el[3], th = el[4];
        float w  = fmaxf(x2 - x1, 1.0f), h = fmaxf(y2 - y1, 1.0f);
        float cx = 0.5f * (x1 + x2),    cy = 0.5f * (y1 + y2);
        g_targets[n * 6 + 0] = (ex - cx) / w;
        g_targets[n * 6 + 1] = (ey - cy) / h;
        g_targets[n * 6 + 2] = logf(fmaxf(2.0f * ea, 0.001f) / w);
        g_targets[n * 6 + 3] = logf(fmaxf(2.0f * eb, 0.001f) / h);
        g_targets[n * 6 + 4] = sinf(2.0f * th);
        g_targets[n * 6 + 5] = cosf(2.0f * th);
    }
}

// ---------------- kernel 3: RoI-align (block per roi) ----------------
__global__ __launch_bounds__(256) void k_roi(const float* __restrict__ features) {
    int n   = blockIdx.x;       // 0..1023
    int b   = n >> 9;
    int tid = threadIdx.x;

    __shared__ int   sy0[14], sx0[14];
    __shared__ float sly[14], slx[14];
    if (tid < 28) {
        float bx1 = g_boxes[n * 4 + 0] * 0.125f;
        float by1 = g_boxes[n * 4 + 1] * 0.125f;
        float bx2 = g_boxes[n * 4 + 2] * 0.125f;
        float by2 = g_boxes[n * 4 + 3] * 0.125f;
        float bw = fmaxf(bx2 - bx1, 1.0f) / 7.0f;
        float bh = fmaxf(by2 - by1, 1.0f) / 7.0f;
        if (tid < 14) {
            float off = ((float)tid + 0.5f) / 2.0f;
            float ys = fminf(fmaxf(by1 + off * bh, 0.0f), 127.0f);
            int y0 = (int)floorf(ys); y0 = min(max(y0, 0), 126);
            sy0[tid] = y0; sly[tid] = ys - (float)y0;
        } else {
            int i = tid - 14;
            float off = ((float)i + 0.5f) / 2.0f;
            float xs = fminf(fmaxf(bx1 + off * bw, 0.0f), 127.0f);
            int x0 = (int)floorf(xs); x0 = min(max(x0, 0), 126);
            sx0[i] = x0; slx[i] = xs - (float)x0;
        }
    }
    __syncthreads();

    const float* fb   = features + (size_t)b * C_FEAT * HF * WF;
    float*       outp = g_pooled + (size_t)n * DIN;

    for (int it = 0; it < 49; it++) {        // 49 * 256 = 12544 exactly
        int e = it * 256 + tid;
        int c = e / 49;
        int r = e - c * 49;
        int py = r / 7, px = r - py * 7;
        const float* fc = fb + (size_t)c * (HF * WF);
        float acc = 0.0f;
#pragma unroll
        for (int sy = 0; sy < 2; sy++) {
            int i = py * 2 + sy;
            int y0 = sy0[i]; float fy = sly[i];
            const float* rowp = fc + y0 * WF;
#pragma unroll
            for (int sx = 0; sx < 2; sx++) {
                int j = px * 2 + sx;
                int x0 = sx0[j]; float fx = slx[j];
                float v00 = __ldg(rowp + x0);
                float v01 = __ldg(rowp + x0 + 1);
                float v10 = __ldg(rowp + WF + x0);
                float v11 = __ldg(rowp + WF + x0 + 1);
                float top = v00 + (v01 - v00) * fx;
                float bot = v10 + (v11 - v10) * fx;
                acc += top + (bot - top) * fy;
            }
        }
        outp[e] = acc * 0.25f;
    }
}

// ---------------- kernel 4: fp32 tiled GEMM + bias + ReLU ----------------
// C[M,N] = relu(A[M,K] @ B[K,N] + bias[N]); 64x64 tile, 256 threads, 4x4 micro-tile
__global__ __launch_bounds__(256) void k_gemm_relu(const float* __restrict__ A,
                                                   const float* __restrict__ B,
                                                   const float* __restrict__ bias,
                                                   float* __restrict__ C,
                                                   int M, int N, int K) {
    __shared__ float As[16][64];   // [k][m] (transposed on store)
    __shared__ float Bs[16][64];   // [k][n]
    int tid = threadIdx.x;
    int m0 = blockIdx.y * 64, n0 = blockIdx.x * 64;
    int ty = tid >> 4, tx = tid & 15;
    int am = tid >> 2,  ak = (tid & 3) * 4;
    int bk = tid >> 4,  bn = (tid & 15) * 4;
    const float* Ap = A + (size_t)(m0 + am) * K + ak;

    float acc[4][4];
#pragma unroll
    for (int i = 0; i < 4; i++)
#pragma unroll
        for (int j = 0; j < 4; j++) acc[i][j] = 0.0f;

    for (int k0 = 0; k0 < K; k0 += 16) {
        float4 av = *(const float4*)(Ap + k0);
        float4 bv = *(const float4*)(B + (size_t)(k0 + bk) * N + n0 + bn);
        As[ak + 0][am] = av.x; As[ak + 1][am] = av.y;
        As[ak + 2][am] = av.z; As[ak + 3][am] = av.w;
        *(float4*)(&Bs[bk][bn]) = bv;
        __syncthreads();
#pragma unroll
        for (int kk = 0; kk < 16; kk++) {
            float4 a  = *(const float4*)(&As[kk][ty * 4]);
            float4 bq = *(const float4*)(&Bs[kk][tx * 4]);
            float ar[4] = {a.x, a.y, a.z, a.w};
            float br_[4] = {bq.x, bq.y, bq.z, bq.w};
#pragma unroll
            for (int i = 0; i < 4; i++)
#pragma unroll
                for (int j = 0; j < 4; j++)
                    acc[i][j] = fmaf(ar[i], br_[j], acc[i][j]);
        }
        __syncthreads();
    }

#pragma unroll
    for (int j = 0; j < 4; j++) {
        float bsv = bias[n0 + tx * 4 + j];
#pragma unroll
        for (int i = 0; i < 4; i++) {
            float v = acc[i][j] + bsv;
            C[(size_t)(m0 + ty * 4 + i) * N + n0 + tx * 4 + j] = fmaxf(v, 0.0f);
        }
    }
}

// ---------------- kernel 5: classification + regression heads ----------------
__global__ __launch_bounds__(128) void k_heads(const float* __restrict__ wc,
                                               const float* __restrict__ bc,
                                               const float* __restrict__ wr,
                                               const float* __restrict__ br) {
    int n = blockIdx.x, tid = threadIdx.x;
    float acc[14];
#pragma unroll
    for (int o = 0; o < 14; o++) acc[o] = 0.0f;
    const float* xr = g_x2 + (size_t)n * HID;
    for (int k = tid; k < HID; k += 128) {
        float xv = xr[k];
        acc[0] = fmaf(xv, wc[k * 2 + 0], acc[0]);
        acc[1] = fmaf(xv, wc[k * 2 + 1], acc[1]);
#pragma unroll
        for (int j = 0; j < 12; j++)
            acc[2 + j] = fmaf(xv, wr[k * 12 + j], acc[2 + j]);
    }
    __shared__ float sh[128];
    for (int o = 0; o < 14; o++) {
        sh[tid] = acc[o]; __syncthreads();
        for (int s = 64; s > 0; s >>= 1) {
            if (tid < s) sh[tid] += sh[tid + s];
            __syncthreads();
        }
        if (tid == 0) {
            float v = sh[0] + (o < 2 ? bc[o] : br[o - 2]);
            if (o < 2) g_logits[n * 2 + o] = v;
            else       g_reg[n * 12 + (o - 2)] = v;
        }
        __syncthreads();
    }
}

// ---------------- kernel 6: losses ----------------
__global__ __launch_bounds__(1024) void k_loss(float* __restrict__ out) {
    int tid = threadIdx.x;
    const float BETA = 1.0f / 9.0f;
    float l0 = g_logits[tid * 2 + 0], l1 = g_logits[tid * 2 + 1];
    int lab = g_labels[tid];
    float mx  = fmaxf(l0, l1);
    float lse = mx + logf(expf(l0 - mx) + expf(l1 - mx));
    float ce  = lse - g_logits[tid * 2 + lab];
    float rl = 0.0f;
    if (lab > 0) {
        const float* pr = g_reg + tid * 12 + lab * 6;
        const float* tg = g_targets + tid * 6;
#pragma unroll
        for (int j = 0; j < 6; j++) {
            float d = fabsf(pr[j] - tg[j]);
            rl += (d < BETA) ? (0.5f * d * d / BETA) : (d - 0.5f * BETA);
        }
    }
    __shared__ float sce[1024];
    __shared__ float srl[1024];
    sce[tid] = ce; srl[tid] = rl;
    __syncthreads();
    for (int s = 512; s > 0; s >>= 1) {
        if (tid < s) { sce[tid] += sce[tid + s]; srl[tid] += srl[tid + s]; }
        __syncthreads();
    }
    if (tid == 0) {
        out[0] = sce[0] / (float)NSAMP;
        out[1] = srl[0] / (float)NSAMP;
    }
}

// ---------------- launch ----------------
extern "C" void kernel_launch(void* const* d_in, const int* in_sizes, int n_in,
                              void* d_out, int out_size) {
    const float* features    = (const float*)d_in[0];
    const float* proposals   = (const float*)d_in[1];
    const float* gt_boxes    = (const float*)d_in[2];
    const int*   gt_labels   = (const int*)  d_in[3];
    const float* gt_ellipses = (const float*)d_in[4];
    const float* w1 = (const float*)d_in[5];
    const float* b1 = (const float*)d_in[6];
    const float* w2 = (const float*)d_in[7];
    const float* b2 = (const float*)d_in[8];
    const float* wc = (const float*)d_in[9];
    const float* bc = (const float*)d_in[10];
    const float* wr = (const float*)d_in[11];
    const float* br = (const float*)d_in[12];
    float* out = (float*)d_out;

    float* px1; float* px2; float* ppool;
    cudaGetSymbolAddress((void**)&ppool, g_pooled);
    cudaGetSymbolAddress((void**)&px1,   g_x1);
    cudaGetSymbolAddress((void**)&px2,   g_x2);

    k_prep<<<dim3(8, 2), 256>>>(proposals, gt_boxes, gt_labels);
    k_sample<<<2, 1024>>>(gt_ellipses);
    k_roi<<<NSAMP, 256>>>(features);
    k_gemm_relu<<<dim3(16, 16), 256>>>(ppool, w1, b1, px1, NSAMP, HID, DIN);
    k_gemm_relu<<<dim3(16, 16), 256>>>(px1,  w2, b2, px2, NSAMP, HID, HID);
    k_heads<<<NSAMP, 128>>>(wc, bc, wr, br);
    k_loss<<<1, 1024>>>(out);
}